// round 17
// baseline (speedup 1.0000x reference)
#include <cuda_runtime.h>
#include <cuda_bf16.h>
#include <cuda_fp16.h>
#include <math.h>
#include <stdint.h>

#define B_   2
#define S_   2048
#define HID_ 2048
#define NH_  32
#define NKV_ 8
#define D_   64

// ---------------------------------------------------------------------------
// Device scratch (no allocations allowed)
// ---------------------------------------------------------------------------
__device__ __half g_qhi[B_*NH_ *S_*D_], g_qlo[B_*NH_ *S_*D_];  // Q fp16 hi/lo (post-RoPE)
__device__ __half g_kh [B_*NKV_*S_*D_];                        // K fp16 (post-RoPE)
__device__ __half g_vh [B_*NKV_*S_*D_];

__device__ __half g_xhi [4096*2048], g_xlo [4096*2048];   // X hi/lo (fp16)
__device__ __half g_wh  [3072*2048];                      // Wq|Wk|Wv fp16
__device__ __half g_woh [2048*2048];                      // Wo fp16
__device__ __half g_aohi[4096*2048], g_aolo[4096*2048];   // attention out hi/lo

// ---------------------------------------------------------------------------
// Baseline-PTX tensor helpers (NO tcgen05 — harness builds plain compute_103)
// ---------------------------------------------------------------------------
__device__ __forceinline__ uint32_t s2u(const void* p) {
    uint32_t a;
    asm("{ .reg .u64 t; cvta.to.shared.u64 t, %1; cvt.u32.u64 %0, t; }"
        : "=r"(a) : "l"(p));
    return a;
}
__device__ __forceinline__ void ldsm4(uint32_t* r, uint32_t addr) {
    asm volatile("ldmatrix.sync.aligned.m8n8.x4.shared.b16 {%0,%1,%2,%3}, [%4];"
        : "=r"(r[0]), "=r"(r[1]), "=r"(r[2]), "=r"(r[3]) : "r"(addr));
}
__device__ __forceinline__ void ldsm4t(uint32_t* r, uint32_t addr) {
    asm volatile("ldmatrix.sync.aligned.m8n8.x4.trans.shared.b16 {%0,%1,%2,%3}, [%4];"
        : "=r"(r[0]), "=r"(r[1]), "=r"(r[2]), "=r"(r[3]) : "r"(addr));
}
__device__ __forceinline__ void mma16816h(float* c, const uint32_t* a, const uint32_t* b) {
    asm volatile("mma.sync.aligned.m16n8k16.row.col.f32.f16.f16.f32 "
        "{%0,%1,%2,%3}, {%4,%5,%6,%7}, {%8,%9}, {%0,%1,%2,%3};"
        : "+f"(c[0]), "+f"(c[1]), "+f"(c[2]), "+f"(c[3])
        : "r"(a[0]), "r"(a[1]), "r"(a[2]), "r"(a[3]), "r"(b[0]), "r"(b[1]));
}
__device__ __forceinline__ void mma16816hacc(uint32_t* c, const uint32_t* a, const uint32_t* b) {
    asm volatile("mma.sync.aligned.m16n8k16.row.col.f16.f16.f16.f16 "
        "{%0,%1}, {%2,%3,%4,%5}, {%6,%7}, {%0,%1};"
        : "+r"(c[0]), "+r"(c[1])
        : "r"(a[0]), "r"(a[1]), "r"(a[2]), "r"(a[3]), "r"(b[0]), "r"(b[1]));
}
__device__ __forceinline__ void cp16(uint32_t saddr, const void* gaddr) {
    asm volatile("cp.async.cg.shared.global [%0], [%1], 16;"
                 :: "r"(saddr), "l"(gaddr));
}
__device__ __forceinline__ uint32_t packf16(float lo, float hi) {
    uint32_t d;
    asm("cvt.rn.f16x2.f32 %0, %1, %2;" : "=r"(d) : "f"(hi), "f"(lo));
    return d;
}
__device__ __forceinline__ __half2 mkh2(float a, float b) {
    __half2 h; h.x = __float2half(a); h.y = __float2half(b); return h;
}

// ---------------------------------------------------------------------------
// Prep: X -> fp16 hi/lo split AND all weights -> fp16, one kernel.
// ---------------------------------------------------------------------------
#define X_F2  (4096*2048/2)
#define WQ_F2 (2048*2048/2)
#define WK_F2 ( 512*2048/2)
#define PREP_TOT (X_F2 + 2*WQ_F2 + 2*WK_F2)

__global__ void prep_all(const float* __restrict__ hs,
                         const float* __restrict__ Wq, const float* __restrict__ Wk,
                         const float* __restrict__ Wv, const float* __restrict__ Wo,
                         __half* __restrict__ xhi, __half* __restrict__ xlo,
                         __half* __restrict__ wh,  __half* __restrict__ woh)
{
    int i = blockIdx.x * blockDim.x + threadIdx.x;
    if (i < X_F2) {
        float2 v = ((const float2*)hs)[i];
        __half h0 = __float2half(v.x);
        __half h1 = __float2half(v.y);
        __half2 hh; hh.x = h0; hh.y = h1;
        __half2 ll; ll.x = __float2half(v.x - __half2float(h0));
        ll.y = __float2half(v.y - __half2float(h1));
        ((__half2*)xhi)[i] = hh;
        ((__half2*)xlo)[i] = ll;
        return;
    }
    int k = i - X_F2;
    const float2* src; __half* dst; int j;
    if (k < WQ_F2)                  { src = (const float2*)Wq; dst = wh;             j = k; }
    else if (k < WQ_F2 + WK_F2)     { src = (const float2*)Wk; dst = wh + 2048*2048; j = k - WQ_F2; }
    else if (k < WQ_F2 + 2*WK_F2)   { src = (const float2*)Wv; dst = wh + 2560*2048; j = k - WQ_F2 - WK_F2; }
    else if (k < 2*WQ_F2 + 2*WK_F2) { src = (const float2*)Wo; dst = woh;            j = k - WQ_F2 - 2*WK_F2; }
    else return;
    float2 v = src[j];
    __half2 h; h.x = __float2half(v.x); h.y = __float2half(v.y);
    ((__half2*)dst)[j] = h;
}

// ---------------------------------------------------------------------------
// fp32-emulated GEMM on fp16 mma.sync (unchanged from passing R16 kernel).
// 128x128 CTA tile, K-chunk 64, 8 warps (4x2), occ 2.
// ---------------------------------------------------------------------------
#define NCHUNK 32      // 2048 / 64
#define GBUF   49152u

__device__ __forceinline__ void load_chunk(
    const __half* __restrict__ Ahi, const __half* __restrict__ Alo,
    const __half* __restrict__ Bh,
    int m0, int n0, uint32_t sb, int buf, int chunk, int tid)
{
    const __half* srcs[3] = {Ahi, Alo, Bh};
    const int r0s[3] = {m0, m0, n0};
    #pragma unroll
    for (int op = 0; op < 3; ++op) {
        #pragma unroll
        for (int j = 0; j < 4; ++j) {
            int u = tid + j * 256;           // 0..1023
            int r = u >> 3, c = u & 7;
            const __half* g =
                srcs[op] + (size_t)(r0s[op] + r) * 2048u + chunk * 64 + c * 8;
            uint32_t so = sb + (uint32_t)buf * GBUF + (uint32_t)op * 16384u
                        + (uint32_t)r * 128u
                        + ((uint32_t)(c ^ (r & 7)) << 4);
            cp16(so, g);
        }
    }
    asm volatile("cp.async.commit_group;" ::: "memory");
}

__global__ __launch_bounds__(256, 2) void gemm_mma(
    const __half* __restrict__ Ahi, const __half* __restrict__ Alo,
    const __half* __restrict__ Bh,
    const float* __restrict__ cosp, const float* __restrict__ sinp,
    int mode, float* __restrict__ outp)
{
    extern __shared__ char smem[];
    const uint32_t sb = s2u(smem);
    const int tid  = threadIdx.x;
    const int lane = tid & 31;
    const int wid  = tid >> 5;
    const int wm   = wid & 3;
    const int wn   = wid >> 2;
    const int m0   = blockIdx.y << 7;
    const int n0   = blockIdx.x << 7;

    float acc[2][8][4];
    #pragma unroll
    for (int mt = 0; mt < 2; ++mt)
        #pragma unroll
        for (int nt = 0; nt < 8; ++nt)
            #pragma unroll
            for (int j = 0; j < 4; ++j) acc[mt][nt][j] = 0.f;

    load_chunk(Ahi, Alo, Bh, m0, n0, sb, 0, 0, tid);

    for (int c = 0; c < NCHUNK; ++c) {
        const int buf = c & 1;
        asm volatile("cp.async.wait_group 0;" ::: "memory");
        __syncthreads();
        if (c + 1 < NCHUNK)
            load_chunk(Ahi, Alo, Bh, m0, n0, sb, buf ^ 1, c + 1, tid);

        const uint32_t base = sb + (uint32_t)buf * GBUF;
        #pragma unroll
        for (int ks = 0; ks < 4; ++ks) {
            const int cg = ks * 2 + (lane >> 4);
            uint32_t ah[2][4], al[2][4];
            #pragma unroll
            for (int mt = 0; mt < 2; ++mt) {
                int r = wm * 32 + mt * 16 + (lane & 15);
                uint32_t sw = (uint32_t)(cg ^ (r & 7)) << 4;
                ldsm4(ah[mt], base +      0u + (uint32_t)r * 128u + sw);
                ldsm4(al[mt], base + 16384u + (uint32_t)r * 128u + sw);
            }
            uint32_t bh[8][2];
            #pragma unroll
            for (int nt2 = 0; nt2 < 4; ++nt2) {
                int r = wn * 64 + nt2 * 16 + (lane & 15);
                uint32_t sw = (uint32_t)(cg ^ (r & 7)) << 4;
                uint32_t t[4];
                ldsm4(t, base + 32768u + (uint32_t)r * 128u + sw);
                bh[nt2*2  ][0] = t[0]; bh[nt2*2  ][1] = t[2];
                bh[nt2*2+1][0] = t[1]; bh[nt2*2+1][1] = t[3];
            }
            #pragma unroll
            for (int mt = 0; mt < 2; ++mt)
                #pragma unroll
                for (int nt = 0; nt < 8; ++nt) {
                    mma16816h(acc[mt][nt], ah[mt], bh[nt]);
                    mma16816h(acc[mt][nt], al[mt], bh[nt]);
                }
        }
    }

    if (mode == 1) {
        #pragma unroll
        for (int mt = 0; mt < 2; ++mt)
            #pragma unroll
            for (int half = 0; half < 2; ++half) {
                const int m = m0 + wm * 32 + mt * 16 + (lane >> 2) + half * 8;
                #pragma unroll
                for (int nt = 0; nt < 8; ++nt) {
                    const int n = n0 + wn * 64 + nt * 8 + (lane & 3) * 2;
                    *(float2*)&outp[(size_t)m * 2048 + n] =
                        make_float2(acc[mt][nt][half*2], acc[mt][nt][half*2+1]);
                }
            }
        return;
    }

    // mode 0: fused RoPE (Q/K) + fp16 conversion.
    #pragma unroll
    for (int mt = 0; mt < 2; ++mt) {
        #pragma unroll
        for (int half = 0; half < 2; ++half) {
            const int m  = m0 + wm * 32 + mt * 16 + (lane >> 2) + half * 8;
            const int bb = m >> 11;
            const int s  = m & 2047;
            const size_t cb = ((size_t)bb * S_ + s) * D_;
            #pragma unroll
            for (int ntp = 0; ntp < 4; ++ntp) {
                const int n = n0 + wn * 64 + ntp * 8 + (lane & 3) * 2;
                float x1a = acc[mt][ntp  ][half*2], x1b = acc[mt][ntp  ][half*2+1];
                float x2a = acc[mt][ntp+4][half*2], x2b = acc[mt][ntp+4][half*2+1];
                if (n < 2560) {
                    const int nn = (n < 2048) ? n : n - 2048;
                    const int h = nn >> 6, d = nn & 63;
                    float2 c1 = *(const float2*)&cosp[cb + d];
                    float2 c2 = *(const float2*)&cosp[cb + d + 32];
                    float2 s1 = *(const float2*)&sinp[cb + d];
                    float2 s2 = *(const float2*)&sinp[cb + d + 32];
                    float y1a = x1a*c1.x - x2a*s1.x;
                    float y1b = x1b*c1.y - x2b*s1.y;
                    float y2a = x2a*c2.x + x1a*s2.x;
                    float y2b = x2b*c2.y + x1b*s2.y;
                    if (n < 2048) {
                        const size_t base = (((size_t)bb*NH_ + h)*S_ + s)*D_ + d;
                        __half2 h1 = mkh2(y1a, y1b), h2v = mkh2(y2a, y2b);
                        *(__half2*)&g_qhi[base]      = h1;
                        *(__half2*)&g_qhi[base + 32] = h2v;
                        *(__half2*)&g_qlo[base] =
                            mkh2(y1a - __half2float(h1.x),  y1b - __half2float(h1.y));
                        *(__half2*)&g_qlo[base + 32] =
                            mkh2(y2a - __half2float(h2v.x), y2b - __half2float(h2v.y));
                    } else {
                        const size_t base = (((size_t)bb*NKV_ + h)*S_ + s)*D_ + d;
                        *(__half2*)&g_kh[base]      = mkh2(y1a, y1b);
                        *(__half2*)&g_kh[base + 32] = mkh2(y2a, y2b);
                    }
                } else {
                    const int nn = n - 2560;
                    const int h = nn >> 6, d = nn & 63;
                    const size_t base = (((size_t)bb*NKV_ + h)*S_ + s)*D_ + d;
                    *(__half2*)&g_vh[base]      = mkh2(x1a, x1b);
                    *(__half2*)&g_vh[base + 32] = mkh2(x2a, x2b);
                }
            }
        }
    }
}

// ---------------------------------------------------------------------------
// Flash attention on mma.sync, occ 2.  KV loaded 128 rows per cp.async window
// (K 16KB | V 16KB per stage, 2 stages), processed as TWO 64-key sub-chunks
// with the exact R16 softmax/PV sequence -> numerics bit-identical, barrier
// windows halved (32 -> 16).
// smem: Q 32KB + 2*32KB = 96KB/CTA, occ 2 = 192KB.
// ---------------------------------------------------------------------------
#define FA_BUF  32768u
#define FA_SMEM (32768 + 2*32768)
#define EXPC    0.180336879f   // 0.125 * log2(e)

__device__ __forceinline__ void fa_load_kv128(const __half* kh, const __half* vb,
                                              int k0, uint32_t sb, int buf, int tid)
{
    #pragma unroll
    for (int j = 0; j < 4; ++j) {
        int u = tid + j * 256;          // 0..1023
        int r = u >> 3, c = u & 7;      // 128 rows x 8 col-groups
        uint32_t so = sb + 32768u + (uint32_t)buf * FA_BUF
                    + (uint32_t)r * 128u + ((uint32_t)(c ^ (r & 7)) << 4);
        cp16(so,          &kh[(size_t)(k0 + r) * 64u + c * 8]);
        cp16(so + 16384u, &vb[(size_t)(k0 + r) * 64u + c * 8]);
    }
    asm volatile("cp.async.commit_group;" ::: "memory");
}

__global__ __launch_bounds__(256, 2) void flash_mma()
{
    extern __shared__ char smem[];
    const uint32_t sb = s2u(smem);
    const int tid  = threadIdx.x;
    const int lane = tid & 31;
    const int wid  = tid >> 5;
    const int q0   = blockIdx.x << 7;
    const int h    = blockIdx.y;
    const int b    = blockIdx.z;
    const int kvh  = h >> 2;

    const __half* qhib = g_qhi + ((size_t)(b*NH_ + h)*S_ + q0)*D_;
    const __half* qlob = g_qlo + ((size_t)(b*NH_ + h)*S_ + q0)*D_;
    const __half* khb  = g_kh  + ((size_t)(b*NKV_ + kvh)*S_)*D_;
    const __half* vbb  = g_vh  + ((size_t)(b*NKV_ + kvh)*S_)*D_;

    #pragma unroll
    for (int j = 0; j < 4; ++j) {
        int u = tid + j * 256;              // 0..1023
        int r = u >> 3, c = u & 7;
        uint32_t so = (uint32_t)r * 128u + ((uint32_t)(c ^ (r & 7)) << 4);
        cp16(sb + so,          &qhib[(size_t)r * 64u + c * 8]);
        cp16(sb + 16384u + so, &qlob[(size_t)r * 64u + c * 8]);
    }
    fa_load_kv128(khb, vbb, 0, sb, 0, tid);   // group: [Q + KV0 (128 rows)]

    float oacc[8][4];
    #pragma unroll
    for (int dt = 0; dt < 8; ++dt)
        #pragma unroll
        for (int j = 0; j < 4; ++j) oacc[dt][j] = 0.f;
    float m0 = -INFINITY, m1 = -INFINITY, l0 = 0.f, l1 = 0.f;   // raw-score units

    const int wrow = wid * 16;
    const uint32_t KH = sb + 32768u;

    for (int c = 0; c < 16; ++c) {            // 16 windows of 128 keys
        const int buf = c & 1;
        asm volatile("cp.async.wait_group 0;" ::: "memory");
        __syncthreads();
        if (c + 1 < 16)
            fa_load_kv128(khb, vbb, (c + 1) * 128, sb, buf ^ 1, tid);

        const uint32_t stage = KH + (uint32_t)buf * FA_BUF;

        #pragma unroll
        for (int sub = 0; sub < 2; ++sub) {   // two 64-key sub-chunks, R16 order
            const uint32_t kh = stage + (uint32_t)sub * 8192u;
            const uint32_t vv = stage + 16384u + (uint32_t)sub * 8192u;

            // ---- S = Q K^T (raw): hi f32 acc + lo f16 acc ----
            float sacc[8][4];
            uint32_t shl[8][2];
            #pragma unroll
            for (int nt = 0; nt < 8; ++nt) {
                #pragma unroll
                for (int j = 0; j < 4; ++j) sacc[nt][j] = 0.f;
                shl[nt][0] = 0u; shl[nt][1] = 0u;
            }

            #pragma unroll
            for (int ks = 0; ks < 4; ++ks) {
                const int cg = ks * 2 + (lane >> 4);
                int rq = wrow + (lane & 15);
                uint32_t swq = (uint32_t)(cg ^ (rq & 7)) << 4;
                uint32_t aqh[4], aql[4];
                ldsm4(aqh, sb +          (uint32_t)rq * 128u + swq);
                ldsm4(aql, sb + 16384u + (uint32_t)rq * 128u + swq);
                uint32_t bh[8][2];
                #pragma unroll
                for (int kb = 0; kb < 4; ++kb) {
                    int rk = kb * 16 + (lane & 15);
                    uint32_t swk = (uint32_t)(cg ^ (rk & 7)) << 4;
                    uint32_t t[4];
                    ldsm4(t, kh + (uint32_t)rk * 128u + swk);
                    bh[kb*2  ][0] = t[0]; bh[kb*2  ][1] = t[2];
                    bh[kb*2+1][0] = t[1]; bh[kb*2+1][1] = t[3];
                }
                #pragma unroll
                for (int nt = 0; nt < 8; ++nt) mma16816h(sacc[nt], aqh, bh[nt]);
                #pragma unroll
                for (int nt = 0; nt < 8; ++nt) mma16816hacc(shl[nt], aql, bh[nt]);
            }
            #pragma unroll
            for (int nt = 0; nt < 8; ++nt) {
                __half2 p01 = *(__half2*)&shl[nt][0];
                __half2 p23 = *(__half2*)&shl[nt][1];
                sacc[nt][0] += __half2float(p01.x);
                sacc[nt][1] += __half2float(p01.y);
                sacc[nt][2] += __half2float(p23.x);
                sacc[nt][3] += __half2float(p23.y);
            }

            // ---- online softmax (exp2-fold + max-skip) ----
            float mx0 = -INFINITY, mx1 = -INFINITY;
            #pragma unroll
            for (int nt = 0; nt < 8; ++nt) {
                mx0 = fmaxf(mx0, fmaxf(sacc[nt][0], sacc[nt][1]));
                mx1 = fmaxf(mx1, fmaxf(sacc[nt][2], sacc[nt][3]));
            }
            #pragma unroll
            for (int off = 1; off < 4; off <<= 1) {
                mx0 = fmaxf(mx0, __shfl_xor_sync(0xffffffffu, mx0, off));
                mx1 = fmaxf(mx1, __shfl_xor_sync(0xffffffffu, mx1, off));
            }
            if (mx0 > m0) {
                float sc0 = exp2f((m0 - mx0) * EXPC);
                m0 = mx0;
                l0 *= sc0;
                #pragma unroll
                for (int dt = 0; dt < 8; ++dt) { oacc[dt][0] *= sc0; oacc[dt][1] *= sc0; }
            }
            if (mx1 > m1) {
                float sc1 = exp2f((m1 - mx1) * EXPC);
                m1 = mx1;
                l1 *= sc1;
                #pragma unroll
                for (int dt = 0; dt < 8; ++dt) { oacc[dt][2] *= sc1; oacc[dt][3] *= sc1; }
            }
            const float nC0 = m0 * EXPC, nC1 = m1 * EXPC;
            float rs0 = 0.f, rs1 = 0.f;
            #pragma unroll
            for (int nt = 0; nt < 8; ++nt) {
                sacc[nt][0] = exp2f(fmaf(sacc[nt][0], EXPC, -nC0));
                sacc[nt][1] = exp2f(fmaf(sacc[nt][1], EXPC, -nC0));
                sacc[nt][2] = exp2f(fmaf(sacc[nt][2], EXPC, -nC1));
                sacc[nt][3] = exp2f(fmaf(sacc[nt][3], EXPC, -nC1));
                rs0 += sacc[nt][0] + sacc[nt][1];
                rs1 += sacc[nt][2] + sacc[nt][3];
            }
            #pragma unroll
            for (int off = 1; off < 4; off <<= 1) {
                rs0 += __shfl_xor_sync(0xffffffffu, rs0, off);
                rs1 += __shfl_xor_sync(0xffffffffu, rs1, off);
            }
            l0 += rs0;
            l1 += rs1;

            // ---- O += P V ----
            #pragma unroll
            for (int ks = 0; ks < 4; ++ks) {
                uint32_t pa[4];
                pa[0] = packf16(sacc[2*ks  ][0], sacc[2*ks  ][1]);
                pa[1] = packf16(sacc[2*ks  ][2], sacc[2*ks  ][3]);
                pa[2] = packf16(sacc[2*ks+1][0], sacc[2*ks+1][1]);
                pa[3] = packf16(sacc[2*ks+1][2], sacc[2*ks+1][3]);
                int rv = ks * 16 + (lane & 7) + ((lane >> 3) & 1) * 8;
                uint32_t rvb = vv + (uint32_t)rv * 128u;
                uint32_t bv[8][2];
                #pragma unroll
                for (int dp = 0; dp < 4; ++dp) {
                    int cv = dp * 2 + (lane >> 4);
                    uint32_t tv[4];
                    ldsm4t(tv, rvb + ((uint32_t)(cv ^ (rv & 7)) << 4));
                    bv[dp*2  ][0] = tv[0]; bv[dp*2  ][1] = tv[1];
                    bv[dp*2+1][0] = tv[2]; bv[dp*2+1][1] = tv[3];
                }
                #pragma unroll
                for (int dt = 0; dt < 8; ++dt)
                    mma16816h(oacc[dt], pa, bv[dt]);
            }
        }
    }

    float inv0 = 1.f / l0, inv1 = 1.f / l1;
    const int r0g = q0 + wrow + (lane >> 2);
    const size_t m0i = ((size_t)(b * S_ + r0g)) * 2048u + h * 64;
    const size_t m1i = m0i + 8u * 2048u;
    #pragma unroll
    for (int dt = 0; dt < 8; ++dt) {
        int d = dt * 8 + (lane & 3) * 2;
        float v0 = oacc[dt][0] * inv0, v1 = oacc[dt][1] * inv0;
        float v2 = oacc[dt][2] * inv1, v3 = oacc[dt][3] * inv1;
        __half2 h01 = mkh2(v0, v1), h23 = mkh2(v2, v3);
        *(__half2*)&g_aohi[m0i + d] = h01;
        *(__half2*)&g_aolo[m0i + d] =
            mkh2(v0 - __half2float(h01.x), v1 - __half2float(h01.y));
        *(__half2*)&g_aohi[m1i + d] = h23;
        *(__half2*)&g_aolo[m1i + d] =
            mkh2(v2 - __half2float(h23.x), v3 - __half2float(h23.y));
    }
}

// ---------------------------------------------------------------------------
extern "C" void kernel_launch(void* const* d_in, const int* in_sizes, int n_in,
                              void* d_out, int out_size)
{
    (void)in_sizes; (void)n_in; (void)out_size;
    const float* hs   = (const float*)d_in[0];
    const float* cosp = (const float*)d_in[1];
    const float* sinp = (const float*)d_in[2];
    const float* Wq = (const float*)d_in[4];
    const float* Wk = (const float*)d_in[5];
    const float* Wv = (const float*)d_in[6];
    const float* Wo = (const float*)d_in[7];
    float* out = (float*)d_out;

    __half *xhi, *xlo, *wh, *woh, *aohi, *aolo;
    cudaGetSymbolAddress((void**)&xhi,  g_xhi);  cudaGetSymbolAddress((void**)&xlo,  g_xlo);
    cudaGetSymbolAddress((void**)&wh,   g_wh);   cudaGetSymbolAddress((void**)&woh,  g_woh);
    cudaGetSymbolAddress((void**)&aohi, g_aohi); cudaGetSymbolAddress((void**)&aolo, g_aolo);

    const int T = 256;
    // 1) all conversions in one launch
    prep_all<<<(PREP_TOT + T-1)/T, T>>>(hs, Wq, Wk, Wv, Wo, xhi, xlo, wh, woh);

    // 2) QKV projection with fused RoPE + fp16 epilogue (K-chunk 64)
    const int gsmem = 2 * (int)GBUF;   // 96KB
    cudaFuncSetAttribute(gemm_mma, cudaFuncAttributeMaxDynamicSharedMemorySize, gsmem);
    dim3 g1(3072/128, 4096/128);
    gemm_mma<<<g1, 256, gsmem>>>(xhi, xlo, wh, cosp, sinp, 0, nullptr);

    // 3) Flash attention (occ 2, 128-key cp.async windows, 64-key sub-chunks)
    cudaFuncSetAttribute(flash_mma, cudaFuncAttributeMaxDynamicSharedMemorySize, FA_SMEM);
    dim3 g2(S_/128, NH_, B_);
    flash_mma<<<g2, 256, FA_SMEM>>>();

    // 4) O-projection (K-chunk 64)
    dim3 g3(2048/128, 4096/128);
    gemm_mma<<<g3, 256, gsmem>>>(aohi, aolo, woh, nullptr, nullptr, 1, out);
}